// round 4
// baseline (speedup 1.0000x reference)
#include <cuda_runtime.h>
#include <cuda_bf16.h>

#define T_STEPS 1000
#define NB 64
#define NH 512
#define NIN 256

// Constants derived exactly as the Python reference does (double math, then fp32 cast)
#define C_MEM  ((float)(0.001 * (1.0 / 1e-2)))     // DT * TAU_MEM_INV   = 0.1
#define C_SYN  ((float)(0.001 * (1.0 / 5e-3)))     // DT * TAU_SYN_INV   = 0.2
#define C_AD   ((float)(0.001 * (1.0 / 800.0)))    // DT * TAU_ADAPT_INV
#define C_JP   ((float)((1.0 / 800.0) * 1.8))      // TAU_ADAPT_INV * BETA

// Scratch: staged input currents (T,B,NH) and transposed recurrent weights (+1 zero pad row)
__device__ __align__(16) float g_xin[(size_t)T_STEPS * NB * NH];
__device__ __align__(16) float g_wrecT[(NH + 1) * NH];

// ---------------------------------------------------------------------------
// Transpose w_rec (NH x NH, row-major [n][m]) -> g_wrecT[m][n]
// ---------------------------------------------------------------------------
__global__ void transpose_wrec(const float* __restrict__ W) {
    __shared__ float tile[32][33];
    int mb = blockIdx.x * 32;
    int nb = blockIdx.y * 32;
    #pragma unroll
    for (int j = threadIdx.y; j < 32; j += 8)
        tile[j][threadIdx.x] = W[(size_t)(nb + j) * NH + mb + threadIdx.x];
    __syncthreads();
    #pragma unroll
    for (int j = threadIdx.y; j < 32; j += 8)
        g_wrecT[(size_t)(mb + j) * NH + nb + threadIdx.x] = tile[threadIdx.x][j];
}

__global__ void zero_pad_row() {
    g_wrecT[(size_t)NH * NH + threadIdx.x] = 0.0f;
}

// ---------------------------------------------------------------------------
// Input GEMM: Y[r,n] = sum_k X[r,k] * Win[n,k]
// Per-element accumulation is STRICTLY sequential over k with fused FMA,
// matching the universal BLAS micro-kernel order (single accumulator, k asc).
// ---------------------------------------------------------------------------
__global__ void __launch_bounds__(256) gemm_in(const float* __restrict__ X,
                                               const float* __restrict__ Win) {
    __shared__ float As[32][68];  // [k][m], padded
    __shared__ float Bs[32][68];  // [k][n], padded

    const int t  = threadIdx.x;
    const int r0 = blockIdx.x * 64;
    const int n0 = blockIdx.y * 64;

    const int lm = t >> 3;         // 0..31
    const int lk = (t & 7) * 4;    // 0,4,...,28

    const int tx = t & 15;         // n sub-tile
    const int ty = t >> 4;         // m sub-tile

    float acc[4][4];
    #pragma unroll
    for (int i = 0; i < 4; i++)
        #pragma unroll
        for (int j = 0; j < 4; j++) acc[i][j] = 0.0f;

    for (int kt = 0; kt < NIN; kt += 32) {
        #pragma unroll
        for (int h = 0; h < 2; h++) {
            int m = lm + 32 * h;
            float4 a = *(const float4*)(X + (size_t)(r0 + m) * NIN + kt + lk);
            As[lk + 0][m] = a.x; As[lk + 1][m] = a.y;
            As[lk + 2][m] = a.z; As[lk + 3][m] = a.w;
            float4 b = *(const float4*)(Win + (size_t)(n0 + m) * NIN + kt + lk);
            Bs[lk + 0][m] = b.x; Bs[lk + 1][m] = b.y;
            Bs[lk + 2][m] = b.z; Bs[lk + 3][m] = b.w;
        }
        __syncthreads();

        #pragma unroll
        for (int kk = 0; kk < 32; kk++) {
            float4 av = *(const float4*)(&As[kk][4 * ty]);
            float4 bv = *(const float4*)(&Bs[kk][4 * tx]);
            float am[4] = {av.x, av.y, av.z, av.w};
            float bn[4] = {bv.x, bv.y, bv.z, bv.w};
            #pragma unroll
            for (int i = 0; i < 4; i++)
                #pragma unroll
                for (int j = 0; j < 4; j++)
                    acc[i][j] = __fmaf_rn(am[i], bn[j], acc[i][j]);
        }
        __syncthreads();
    }

    #pragma unroll
    for (int i = 0; i < 4; i++) {
        float4 o = make_float4(acc[i][0], acc[i][1], acc[i][2], acc[i][3]);
        *(float4*)(g_xin + (size_t)(r0 + 4 * ty + i) * NH + n0 + 4 * tx) = o;
    }
}

// ---------------------------------------------------------------------------
// Persistent recurrent kernel: 1 CTA per batch element, 256 threads,
// each thread owns 2 consecutive neurons.
// Recurrent term: index-ordered sparse gather with sequential __fadd_rn,
// bit-identical to a dense fused sequential dot with z in {0,1}.
// Elementwise update: FMA-CONTRACTED forms (LLVM canonical contraction),
// matching XLA's backend codegen:
//   v_dec = fma(C_MEM, (0-v)+i, v)
//   b_dec = fma(C_AD, 1-b, b)
//   i_dec = fma(-C_SYN, i, i)
// v_new / b_new are contraction-invariant because z is exactly 0 or 1.
// ---------------------------------------------------------------------------
__global__ void __launch_bounds__(256, 1) lsnn_recurrent(
    const float* __restrict__ z0, const float* __restrict__ v0,
    const float* __restrict__ i0, const float* __restrict__ b0,
    float* __restrict__ out, int write_tail) {

    const int b    = blockIdx.x;
    const int tid  = threadIdx.x;
    const int lane = tid & 31;
    const int wrp  = tid >> 5;
    const int n2   = tid * 2;

    __shared__ __align__(16) int s_list[NH + 8];
    __shared__ int s_wsum[8];
    __shared__ int s_wbase[8];
    __shared__ int s_cnt;

    const size_t sb = (size_t)b * NH + n2;
    float2 v  = *(const float2*)(v0 + sb);
    float2 cu = *(const float2*)(i0 + sb);
    float2 ba = *(const float2*)(b0 + sb);
    float2 z  = *(const float2*)(z0 + sb);

    // ---- build spike list in ascending neuron-index order (deterministic) ----
    auto build = [&](float2 zz) {
        int c0 = (zz.x != 0.0f) ? 1 : 0;
        int c1 = (zz.y != 0.0f) ? 1 : 0;
        int my = c0 + c1;
        int pref = my;
        #pragma unroll
        for (int d = 1; d < 32; d <<= 1) {
            int o = __shfl_up_sync(0xffffffffu, pref, d);
            if (lane >= d) pref += o;
        }
        if (lane == 31) s_wsum[wrp] = pref;
        int excl = pref - my;
        __syncthreads();
        if (tid == 0) {
            int s = 0;
            #pragma unroll
            for (int w = 0; w < 8; w++) { s_wbase[w] = s; s += s_wsum[w]; }
            int p = s;
            while (p & 7) s_list[p++] = NH;   // pad with zero-row index (adds +0.0, exact)
            s_cnt = p;
        }
        __syncthreads();
        int pos = s_wbase[wrp] + excl;
        if (c0) s_list[pos++] = n2;
        if (c1) s_list[pos]   = n2 + 1;
        __syncthreads();
    };

    build(z);  // list for the z0 carry

    const float* xin_p = g_xin + sb;
    float*       out_p = out + sb;

    for (int t = 0; t < T_STEPS; t++) {
        // ---- recurrent gather: rec[n] = sum over spiking m (ascending) of w_recT[m][n]
        // STRICT sequential accumulation order.
        float recx = 0.0f, recy = 0.0f;
        const int cnt = s_cnt;
        for (int k = 0; k < cnt; k += 8) {
            int4 ma = *(const int4*)(s_list + k);
            int4 mb = *(const int4*)(s_list + k + 4);
            float2 w0 = *(const float2*)(g_wrecT + (size_t)ma.x * NH + n2);
            float2 w1 = *(const float2*)(g_wrecT + (size_t)ma.y * NH + n2);
            float2 w2 = *(const float2*)(g_wrecT + (size_t)ma.z * NH + n2);
            float2 w3 = *(const float2*)(g_wrecT + (size_t)ma.w * NH + n2);
            float2 w4 = *(const float2*)(g_wrecT + (size_t)mb.x * NH + n2);
            float2 w5 = *(const float2*)(g_wrecT + (size_t)mb.y * NH + n2);
            float2 w6 = *(const float2*)(g_wrecT + (size_t)mb.z * NH + n2);
            float2 w7 = *(const float2*)(g_wrecT + (size_t)mb.w * NH + n2);
            recx = __fadd_rn(recx, w0.x); recy = __fadd_rn(recy, w0.y);
            recx = __fadd_rn(recx, w1.x); recy = __fadd_rn(recy, w1.y);
            recx = __fadd_rn(recx, w2.x); recy = __fadd_rn(recy, w2.y);
            recx = __fadd_rn(recx, w3.x); recy = __fadd_rn(recy, w3.y);
            recx = __fadd_rn(recx, w4.x); recy = __fadd_rn(recy, w4.y);
            recx = __fadd_rn(recx, w5.x); recy = __fadd_rn(recy, w5.y);
            recx = __fadd_rn(recx, w6.x); recy = __fadd_rn(recy, w6.y);
            recx = __fadd_rn(recx, w7.x); recy = __fadd_rn(recy, w7.y);
        }

        float2 xin = *(const float2*)(xin_p);
        xin_p += NB * NH;

        // ---- elementwise LSNN update: FMA-contracted (LLVM canonical) ----
        // v_dec = fma(C_MEM, (0 - v) + i, v)
        float vd0 = __fmaf_rn(C_MEM, __fadd_rn(__fsub_rn(0.0f, v.x), cu.x), v.x);
        float vd1 = __fmaf_rn(C_MEM, __fadd_rn(__fsub_rn(0.0f, v.y), cu.y), v.y);
        // b_dec = fma(C_AD, 1 - b, b)
        float bd0 = __fmaf_rn(C_AD, __fsub_rn(1.0f, ba.x), ba.x);
        float bd1 = __fmaf_rn(C_AD, __fsub_rn(1.0f, ba.y), ba.y);
        // z_new = heaviside(v_dec - b_dec)
        float zz0 = (__fsub_rn(vd0, bd0) > 0.0f) ? 1.0f : 0.0f;
        float zz1 = (__fsub_rn(vd1, bd1) > 0.0f) ? 1.0f : 0.0f;
        // v_new = (1 - z)*v_dec + z*0   (exact for z in {0,1})
        v.x = (zz0 != 0.0f) ? 0.0f : __fadd_rn(vd0, 0.0f);
        v.y = (zz1 != 0.0f) ? 0.0f : __fadd_rn(vd1, 0.0f);
        // b_new = b_dec + z*C_JP        (exact for z in {0,1})
        ba.x = __fadd_rn(bd0, (zz0 != 0.0f) ? C_JP : 0.0f);
        ba.y = __fadd_rn(bd1, (zz1 != 0.0f) ? C_JP : 0.0f);
        // i_dec = fma(-C_SYN, i, i) ; i_new = (i_dec + xin) + rec
        float id0 = __fmaf_rn(-C_SYN, cu.x, cu.x);
        float id1 = __fmaf_rn(-C_SYN, cu.y, cu.y);
        cu.x = __fadd_rn(__fadd_rn(id0, xin.x), recx);
        cu.y = __fadd_rn(__fadd_rn(id1, xin.y), recy);
        z.x = zz0;
        z.y = zz1;

        *(float2*)(out_p) = z;
        out_p += NB * NH;

        build(z);  // list for next step's carry (internal syncs order vs. gather)
    }

    if (write_tail) {
        size_t base = (size_t)T_STEPS * NB * NH;
        *(float2*)(out + base + 0 * (size_t)NB * NH + sb) = z;
        *(float2*)(out + base + 1 * (size_t)NB * NH + sb) = v;
        *(float2*)(out + base + 2 * (size_t)NB * NH + sb) = cu;
        *(float2*)(out + base + 3 * (size_t)NB * NH + sb) = ba;
    }
}

// ---------------------------------------------------------------------------
extern "C" void kernel_launch(void* const* d_in, const int* in_sizes, int n_in,
                              void* d_out, int out_size) {
    const float* x     = (const float*)d_in[0];
    const float* z0    = (const float*)d_in[1];
    const float* v0    = (const float*)d_in[2];
    const float* i0    = (const float*)d_in[3];
    const float* b0    = (const float*)d_in[4];
    const float* w_in  = (const float*)d_in[5];
    const float* w_rec = (const float*)d_in[6];
    float* out = (float*)d_out;

    transpose_wrec<<<dim3(16, 16), dim3(32, 8)>>>(w_rec);
    zero_pad_row<<<1, NH>>>();
    gemm_in<<<dim3((T_STEPS * NB) / 64, NH / 64), 256>>>(x, w_in);

    long long need = (long long)T_STEPS * NB * NH + 4LL * NB * NH;
    int write_tail = ((long long)out_size >= need) ? 1 : 0;
    lsnn_recurrent<<<NB, 256>>>(z0, v0, i0, b0, out, write_tail);
}